// round 9
// baseline (speedup 1.0000x reference)
#include <cuda_runtime.h>
#include <cuda_bf16.h>
#include <cstdint>

#define EMBED   1024
#define NHEADS  16
#define HDIM    64
#define BATCH   2
#define SEQ     2048
#define MROWS   (BATCH*SEQ)   // 4096

#define NEG_INF (-1e30f)

typedef __nv_bfloat16 bf;

// NOTE: tcgen05 is NOT usable here — the harness emits compute_103 PTX (no
// 'a' feature target) and ptxas rejects tcgen05.* at that target. All tensor
// work goes through mma.sync (HMMA). The split-bf16 (Markidis) trick gives
// ~fp32 accuracy with 3 bf16 MMAs per logical MMA.

// ---------------------------------------------------------------------------
// Scratch (device globals — no allocation allowed). Everything bf16 hi/lo.
// ---------------------------------------------------------------------------
__device__ bf g_Xh[(size_t)MROWS*EMBED],   g_Xl[(size_t)MROWS*EMBED];
__device__ bf g_Wqh[(size_t)3*EMBED*EMBED], g_Wql[(size_t)3*EMBED*EMBED];
__device__ bf g_Woh[(size_t)EMBED*EMBED],  g_Wol[(size_t)EMBED*EMBED];
__device__ bf g_Qh[(size_t)MROWS*EMBED],   g_Ql[(size_t)MROWS*EMBED];
__device__ bf g_Kh[(size_t)MROWS*EMBED],   g_Kl[(size_t)MROWS*EMBED];
__device__ bf g_Vh[(size_t)MROWS*EMBED],   g_Vl[(size_t)MROWS*EMBED];
__device__ bf g_Ch[(size_t)MROWS*EMBED],   g_Cl[(size_t)MROWS*EMBED];

// ---------------------------------------------------------------------------
// PTX helpers
// ---------------------------------------------------------------------------
__device__ __forceinline__ uint32_t saddr(const void* p) {
    return (uint32_t)__cvta_generic_to_shared(p);
}
__device__ __forceinline__ void cpa16(uint32_t dst, const void* src) {
    asm volatile("cp.async.cg.shared.global [%0], [%1], 16;\n" :: "r"(dst), "l"(src));
}
__device__ __forceinline__ void cpa_commit() {
    asm volatile("cp.async.commit_group;\n");
}
template<int N>
__device__ __forceinline__ void cpa_wait() {
    asm volatile("cp.async.wait_group %0;\n" :: "n"(N));
}
__device__ __forceinline__ void ldsm_x4(uint32_t& r0, uint32_t& r1,
                                        uint32_t& r2, uint32_t& r3, uint32_t a) {
    asm volatile("ldmatrix.sync.aligned.m8n8.x4.shared.b16 {%0,%1,%2,%3}, [%4];"
                 : "=r"(r0), "=r"(r1), "=r"(r2), "=r"(r3) : "r"(a));
}
__device__ __forceinline__ void ldsm_x4_t(uint32_t& r0, uint32_t& r1,
                                          uint32_t& r2, uint32_t& r3, uint32_t a) {
    asm volatile("ldmatrix.sync.aligned.m8n8.x4.trans.shared.b16 {%0,%1,%2,%3}, [%4];"
                 : "=r"(r0), "=r"(r1), "=r"(r2), "=r"(r3) : "r"(a));
}
// NON-volatile: register-only op, lets ptxas schedule/pipeline HMMAs.
__device__ __forceinline__ void mma_bf16(float* c, const uint32_t* a, const uint32_t* b) {
    asm("mma.sync.aligned.m16n8k16.row.col.f32.bf16.bf16.f32 "
        "{%0,%1,%2,%3}, {%4,%5,%6,%7}, {%8,%9}, {%0,%1,%2,%3};"
        : "+f"(c[0]), "+f"(c[1]), "+f"(c[2]), "+f"(c[3])
        : "r"(a[0]), "r"(a[1]), "r"(a[2]), "r"(a[3]), "r"(b[0]), "r"(b[1]));
}
__device__ __forceinline__ uint32_t pk(bf a, bf b) {
    return (uint32_t)__bfloat16_as_ushort(a) | ((uint32_t)__bfloat16_as_ushort(b) << 16);
}
__device__ __forceinline__ void split_pack(float a, float b, uint32_t& hi, uint32_t& lo) {
    bf ah = __float2bfloat16(a), bh = __float2bfloat16(b);
    hi = pk(ah, bh);
    lo = pk(__float2bfloat16(a - __bfloat162float(ah)),
            __float2bfloat16(b - __bfloat162float(bh)));
}
__device__ __forceinline__ void cvt_store4(float4 f, bf* hp, bf* lp) {
    uint32_t h0, l0, h1, l1;
    split_pack(f.x, f.y, h0, l0);
    split_pack(f.z, f.w, h1, l1);
    uint2 hv; hv.x = h0; hv.y = h1;
    uint2 lv; lv.x = l0; lv.y = l1;
    *(uint2*)hp = hv;
    *(uint2*)lp = lv;
}

// ---------------------------------------------------------------------------
// Input conversion pre-pass: split x, w_qkv, w_out into bf16 hi/lo globals.
// ---------------------------------------------------------------------------
__global__ __launch_bounds__(256)
void cvt_inputs(const float* __restrict__ x, const float* __restrict__ wq,
                const float* __restrict__ wo)
{
    const int i = blockIdx.x * 256 + threadIdx.x;
    const float* src; bf *dh, *dl; int off;
    if (i < 1048576)            { src = x;  dh = g_Xh;  dl = g_Xl;  off = i; }
    else if (i < 1048576+786432){ src = wq; dh = g_Wqh; dl = g_Wql; off = i - 1048576; }
    else                        { src = wo; dh = g_Woh; dl = g_Wol; off = i - 1835008; }
    float4 f = ((const float4*)src)[off];
    cvt_store4(f, dh + (size_t)off*4, dl + (size_t)off*4);
}

// ---------------------------------------------------------------------------
// Pipelined tensor-core GEMM (split-bf16): out = A @ Bw^T + bias
// 256 threads, CTA tile 128x128, 8 warps (2m x 4n), warp tile 64x32.
// K-step 32, 2-stage cp.async pipeline, 2 CTAs/SM.
// Split-term MMAs reordered term-outer/n-inner: same-accumulator reuse is
// 4 HMMAs apart (breaks the 3-deep RAW chain that capped tensor util ~46%).
// MODE 0: A=g_X, B=g_Wq, epilogue scatters split Q/K/V.
// MODE 1: A=g_C, B=g_Wo, epilogue fp32 C.
// ---------------------------------------------------------------------------
#define GSTAGE_B  40960
#define GEMM_SMEM (2*GSTAGE_B)   // 81920 -> 2 CTAs/SM

template<int MODE>
__global__ __launch_bounds__(256, 2)
void gemm_tc4(const float* __restrict__ bias, float* __restrict__ C,
              int M, int N, int K)
{
    extern __shared__ bf sm[];
    const uint32_t smem0 = saddr(sm);

    const bf* Ahp = (MODE == 0) ? g_Xh : g_Ch;
    const bf* Alp = (MODE == 0) ? g_Xl : g_Cl;
    const bf* Bhp = (MODE == 0) ? g_Wqh : g_Woh;
    const bf* Blp = (MODE == 0) ? g_Wql : g_Wol;

    const int tid  = threadIdx.x;
    const int lane = tid & 31;
    const int warp = tid >> 5;
    const int wm   = warp >> 2;
    const int wn   = warp & 3;
    const int bm   = blockIdx.y * 128;
    const int bn   = blockIdx.x * 128;

    const int lr   = tid >> 1;
    const int half = tid & 1;

    const bf* a0 = Ahp + (size_t)(bm + lr) * K + half*16;
    const bf* a1 = Alp + (size_t)(bm + lr) * K + half*16;
    const bf* b0 = Bhp + (size_t)(bn + lr) * K + half*16;
    const bf* b1 = Blp + (size_t)(bn + lr) * K + half*16;
    const uint32_t dbase = smem0 + lr*80 + half*32;

    const int nsteps = K >> 5;

    auto copy_stage = [&](int k0, int stg) {
        const uint32_t d = dbase + stg * GSTAGE_B;
        cpa16(d,          a0 + k0);  cpa16(d + 16,         a0 + k0 + 8);
        cpa16(d + 10240,  a1 + k0);  cpa16(d + 10240 + 16, a1 + k0 + 8);
        cpa16(d + 20480,  b0 + k0);  cpa16(d + 20480 + 16, b0 + k0 + 8);
        cpa16(d + 30720,  b1 + k0);  cpa16(d + 30720 + 16, b1 + k0 + 8);
    };

    float acc[16][4];
    #pragma unroll
    for (int i = 0; i < 16; i++)
        #pragma unroll
        for (int j = 0; j < 4; j++) acc[i][j] = 0.f;

    const int arow = wm*64 + (lane & 15);
    const int acol = ((lane >> 4) & 1) * 8;
    const int brow = wn*32 + (lane & 7) + ((lane >> 4) & 1) * 8;
    const int bcol = ((lane >> 3) & 1) * 8;
    const uint32_t aoff = (uint32_t)(arow*80 + acol*2);
    const uint32_t boff = (uint32_t)(20480 + brow*80 + bcol*2);

    copy_stage(0, 0);  cpa_commit();

    for (int ks = 0; ks < nsteps; ks++) {
        const int nk = ks + 1;
        if (nk < nsteps) copy_stage(nk*32, nk & 1);
        cpa_commit();
        cpa_wait<1>();
        __syncthreads();

        const uint32_t base = smem0 + (ks & 1) * GSTAGE_B;

        #pragma unroll
        for (int kk = 0; kk < 2; kk++) {
            const uint32_t ab  = base + aoff + kk*32;
            const uint32_t bbx = base + boff + kk*32;
            // B fragments (live across the t loop)
            uint32_t bh[2][4], bl[2][4];
            #pragma unroll
            for (int p = 0; p < 2; p++) {
                ldsm_x4(bh[p][0], bh[p][1], bh[p][2], bh[p][3], bbx + p*1280);
                ldsm_x4(bl[p][0], bl[p][1], bl[p][2], bl[p][3], bbx + 10240 + p*1280);
            }
            #pragma unroll
            for (int t = 0; t < 4; t++) {
                uint32_t ah[4], al[4];
                ldsm_x4(ah[0], ah[1], ah[2], ah[3], ab + t*1280);
                ldsm_x4(al[0], al[1], al[2], al[3], ab + 10240 + t*1280);
                // term-outer, n-inner: same-acc reuse spaced by 4 HMMAs
                #pragma unroll
                for (int n = 0; n < 4; n++)
                    mma_bf16(acc[t*4 + n], ah, &bh[n >> 1][(n & 1) * 2]);
                #pragma unroll
                for (int n = 0; n < 4; n++)
                    mma_bf16(acc[t*4 + n], ah, &bl[n >> 1][(n & 1) * 2]);
                #pragma unroll
                for (int n = 0; n < 4; n++)
                    mma_bf16(acc[t*4 + n], al, &bh[n >> 1][(n & 1) * 2]);
            }
        }
        __syncthreads();
    }

    // epilogue
    #pragma unroll
    for (int t = 0; t < 4; t++) {
        const int r0 = bm + wm*64 + t*16 + (lane >> 2);
        #pragma unroll
        for (int n = 0; n < 4; n++) {
            const int col = bn + wn*32 + n*8 + (lane & 3)*2;
            const float b0v = bias[col], b1v = bias[col + 1];
            const float* c = acc[t*4 + n];
            if (MODE == 0) {
                const int sel = col >> 10;      // 0=Q 1=K 2=V
                const int e   = col & 1023;
                bf* ph = (sel == 0) ? g_Qh : (sel == 1) ? g_Kh : g_Vh;
                bf* pl = (sel == 0) ? g_Ql : (sel == 1) ? g_Kl : g_Vl;
                const int hh = e >> 6, dd = e & 63;
                #pragma unroll
                for (int rr = 0; rr < 2; rr++) {
                    const int row = r0 + rr*8;
                    const int bbv = row >> 11, ss = row & 2047;
                    const size_t idx = (((size_t)(bbv*NHEADS + hh))*SEQ + ss)*HDIM + dd;
                    uint32_t hi, lo;
                    split_pack(c[rr*2] + b0v, c[rr*2+1] + b1v, hi, lo);
                    *(uint32_t*)&ph[idx] = hi;
                    *(uint32_t*)&pl[idx] = lo;
                }
            } else {
                float2 v0; v0.x = c[0] + b0v; v0.y = c[1] + b1v;
                float2 v1; v1.x = c[2] + b0v; v1.y = c[3] + b1v;
                *(float2*)&C[(size_t)r0       * N + col] = v0;
                *(float2*)&C[(size_t)(r0 + 8) * N + col] = v1;
            }
        }
    }
}

// ---------------------------------------------------------------------------
// Tensor-core flash attention (causal), split-bf16, cp.async loads.
// Split-term MMAs reordered term-outer/nt-inner (8-apart acc reuse).
// ---------------------------------------------------------------------------
#define ATTN_SMEM_BYTES 73728

__global__ __launch_bounds__(256, 1)
void attn_tc()
{
    extern __shared__ bf sb[];
    bf (*Qh)[72] = (bf(*)[72])(sb);
    bf (*Ql)[72] = (bf(*)[72])(sb + 9216);
    bf (*Kh)[72] = (bf(*)[72])(sb + 18432);
    bf (*Kl)[72] = (bf(*)[72])(sb + 23040);
    bf (*Vh)[72] = (bf(*)[72])(sb + 27648);
    bf (*Vl)[72] = (bf(*)[72])(sb + 32256);

    const int qt   = (int)(gridDim.x - 1) - (int)blockIdx.x;
    const int bhid = blockIdx.y;
    const int bb   = bhid / NHEADS;
    const int hh   = bhid % NHEADS;

    const size_t hb = (size_t)bhid * SEQ * HDIM;

    const int tid  = threadIdx.x;
    const int lane = tid & 31;
    const int w    = tid >> 5;
    const int qbase = qt * 128;

    {
        const int lr = tid >> 1, hf = tid & 1;
        const bf* qh = g_Qh + hb + (size_t)(qbase + lr)*HDIM + hf*32;
        const bf* ql = g_Ql + hb + (size_t)(qbase + lr)*HDIM + hf*32;
        const uint32_t dh = saddr(&Qh[lr][hf*32]);
        const uint32_t dl = saddr(&Ql[lr][hf*32]);
        #pragma unroll
        for (int u = 0; u < 4; u++) {
            cpa16(dh + u*16, qh + u*8);
            cpa16(dl + u*16, ql + u*8);
        }
        cpa_commit();
        cpa_wait<0>();
    }
    __syncthreads();

    uint32_t qfh[4][4], qfl[4][4];
    {
        const int arow = w*16 + (lane & 15);
        const int acol = ((lane >> 4) & 1) * 8;
        #pragma unroll
        for (int kc = 0; kc < 4; kc++) {
            ldsm_x4(qfh[kc][0], qfh[kc][1], qfh[kc][2], qfh[kc][3],
                    saddr(&Qh[arow][kc*16 + acol]));
            ldsm_x4(qfl[kc][0], qfl[kc][1], qfl[kc][2], qfl[kc][3],
                    saddr(&Ql[arow][kc*16 + acol]));
        }
    }

    float O[8][4];
    #pragma unroll
    for (int nt = 0; nt < 8; nt++)
        #pragma unroll
        for (int e = 0; e < 4; e++) O[nt][e] = 0.f;

    float m0 = NEG_INF, m1 = NEG_INF, l0 = 0.f, l1 = 0.f;
    const int r0g = qbase + w*16 + (lane >> 2);
    const int r1g = r0g + 8;
    const int wr  = qbase + w*16;

    const int krow = (lane & 7) + ((lane >> 4) & 1) * 8;
    const int kcol = ((lane >> 3) & 1) * 8;
    const int vrow = (lane & 7) + ((lane >> 3) & 1) * 8;
    const int vcol = ((lane >> 4) & 1) * 8;

    const int kr = tid >> 2, q4 = tid & 3;

    const int nktiles = 2*qt + 2;
    for (int kt = 0; kt < nktiles; kt++) {
        const int kbase = kt * 64;
        __syncthreads();

        {
            const size_t srcoff = hb + (size_t)(kbase + kr)*HDIM + q4*16;
            const uint32_t doff = (uint32_t)(kr*144 + q4*32);
            const uint32_t kh = saddr(Kh) + doff, kl = saddr(Kl) + doff;
            const uint32_t vh = saddr(Vh) + doff, vl = saddr(Vl) + doff;
            cpa16(kh, g_Kh + srcoff);  cpa16(kh + 16, g_Kh + srcoff + 8);
            cpa16(kl, g_Kl + srcoff);  cpa16(kl + 16, g_Kl + srcoff + 8);
            cpa16(vh, g_Vh + srcoff);  cpa16(vh + 16, g_Vh + srcoff + 8);
            cpa16(vl, g_Vl + srcoff);  cpa16(vl + 16, g_Vl + srcoff + 8);
            cpa_commit();
            cpa_wait<0>();
        }
        __syncthreads();

        if (wr + 15 < kbase) continue;

        float s[8][4];
        #pragma unroll
        for (int nt = 0; nt < 8; nt++)
            #pragma unroll
            for (int e = 0; e < 4; e++) s[nt][e] = 0.f;

        #pragma unroll
        for (int kc = 0; kc < 4; kc++) {
            uint32_t kh4[4][4], kl4[4][4];
            #pragma unroll
            for (int p = 0; p < 4; p++) {
                ldsm_x4(kh4[p][0], kh4[p][1], kh4[p][2], kh4[p][3],
                        saddr(&Kh[p*16 + krow][kc*16 + kcol]));
                ldsm_x4(kl4[p][0], kl4[p][1], kl4[p][2], kl4[p][3],
                        saddr(&Kl[p*16 + krow][kc*16 + kcol]));
            }
            // term-outer, nt-inner: same-acc reuse spaced by 8 HMMAs
            #pragma unroll
            for (int nt = 0; nt < 8; nt++)
                mma_bf16(s[nt], qfh[kc], &kh4[nt >> 1][(nt & 1) * 2]);
            #pragma unroll
            for (int nt = 0; nt < 8; nt++)
                mma_bf16(s[nt], qfh[kc], &kl4[nt >> 1][(nt & 1) * 2]);
            #pragma unroll
            for (int nt = 0; nt < 8; nt++)
                mma_bf16(s[nt], qfl[kc], &kh4[nt >> 1][(nt & 1) * 2]);
        }

        #pragma unroll
        for (int nt = 0; nt < 8; nt++)
            #pragma unroll
            for (int e = 0; e < 4; e++) s[nt][e] *= 0.125f;

        if (kbase + 63 > wr) {
            #pragma unroll
            for (int nt = 0; nt < 8; nt++) {
                const int c0 = kbase + nt*8 + ((lane & 3) << 1);
                if (c0     > r0g) s[nt][0] = NEG_INF;
                if (c0 + 1 > r0g) s[nt][1] = NEG_INF;
                if (c0     > r1g) s[nt][2] = NEG_INF;
                if (c0 + 1 > r1g) s[nt][3] = NEG_INF;
            }
        }

        float mx0 = NEG_INF, mx1 = NEG_INF;
        #pragma unroll
        for (int nt = 0; nt < 8; nt++) {
            mx0 = fmaxf(mx0, fmaxf(s[nt][0], s[nt][1]));
            mx1 = fmaxf(mx1, fmaxf(s[nt][2], s[nt][3]));
        }
        mx0 = fmaxf(mx0, __shfl_xor_sync(0xffffffffu, mx0, 1));
        mx0 = fmaxf(mx0, __shfl_xor_sync(0xffffffffu, mx0, 2));
        mx1 = fmaxf(mx1, __shfl_xor_sync(0xffffffffu, mx1, 1));
        mx1 = fmaxf(mx1, __shfl_xor_sync(0xffffffffu, mx1, 2));

        const float nm0 = fmaxf(m0, mx0);
        const float nm1 = fmaxf(m1, mx1);
        const float f0 = __expf(m0 - nm0);
        const float f1 = __expf(m1 - nm1);

        float ps0 = 0.f, ps1 = 0.f;
        #pragma unroll
        for (int nt = 0; nt < 8; nt++) {
            s[nt][0] = __expf(s[nt][0] - nm0);
            s[nt][1] = __expf(s[nt][1] - nm0);
            s[nt][2] = __expf(s[nt][2] - nm1);
            s[nt][3] = __expf(s[nt][3] - nm1);
            ps0 += s[nt][0] + s[nt][1];
            ps1 += s[nt][2] + s[nt][3];
        }
        ps0 += __shfl_xor_sync(0xffffffffu, ps0, 1);
        ps0 += __shfl_xor_sync(0xffffffffu, ps0, 2);
        ps1 += __shfl_xor_sync(0xffffffffu, ps1, 1);
        ps1 += __shfl_xor_sync(0xffffffffu, ps1, 2);

        l0 = l0 * f0 + ps0;  m0 = nm0;
        l1 = l1 * f1 + ps1;  m1 = nm1;

        #pragma unroll
        for (int nt = 0; nt < 8; nt++) {
            O[nt][0] *= f0; O[nt][1] *= f0;
            O[nt][2] *= f1; O[nt][3] *= f1;
        }

        #pragma unroll
        for (int kc = 0; kc < 4; kc++) {
            uint32_t pah[4], pal[4];
            split_pack(s[2*kc  ][0], s[2*kc  ][1], pah[0], pal[0]);
            split_pack(s[2*kc  ][2], s[2*kc  ][3], pah[1], pal[1]);
            split_pack(s[2*kc+1][0], s[2*kc+1][1], pah[2], pal[2]);
            split_pack(s[2*kc+1][2], s[2*kc+1][3], pah[3], pal[3]);

            uint32_t vh4[4][4], vl4[4][4];
            #pragma unroll
            for (int p = 0; p < 4; p++) {
                ldsm_x4_t(vh4[p][0], vh4[p][1], vh4[p][2], vh4[p][3],
                          saddr(&Vh[kc*16 + vrow][p*16 + vcol]));
                ldsm_x4_t(vl4[p][0], vl4[p][1], vl4[p][2], vl4[p][3],
                          saddr(&Vl[kc*16 + vrow][p*16 + vcol]));
            }
            // term-outer, nt-inner
            #pragma unroll
            for (int nt = 0; nt < 8; nt++)
                mma_bf16(O[nt], pah, &vh4[nt >> 1][(nt & 1) * 2]);
            #pragma unroll
            for (int nt = 0; nt < 8; nt++)
                mma_bf16(O[nt], pah, &vl4[nt >> 1][(nt & 1) * 2]);
            #pragma unroll
            for (int nt = 0; nt < 8; nt++)
                mma_bf16(O[nt], pal, &vh4[nt >> 1][(nt & 1) * 2]);
        }
    }

    const float inv0 = 1.f / l0;
    const float inv1 = 1.f / l1;
    const size_t i0 = ((size_t)bb*SEQ + r0g)*EMBED + hh*HDIM;
    const size_t i1 = ((size_t)bb*SEQ + r1g)*EMBED + hh*HDIM;
    #pragma unroll
    for (int nt = 0; nt < 8; nt++) {
        const int c = nt*8 + (lane & 3)*2;
        uint32_t hi, lo;
        split_pack(O[nt][0]*inv0, O[nt][1]*inv0, hi, lo);
        *(uint32_t*)&g_Ch[i0 + c] = hi;
        *(uint32_t*)&g_Cl[i0 + c] = lo;
        split_pack(O[nt][2]*inv1, O[nt][3]*inv1, hi, lo);
        *(uint32_t*)&g_Ch[i1 + c] = hi;
        *(uint32_t*)&g_Cl[i1 + c] = lo;
    }
}

// ---------------------------------------------------------------------------
extern "C" void kernel_launch(void* const* d_in, const int* in_sizes, int n_in,
                              void* d_out, int out_size)
{
    const float* x     = (const float*)d_in[0];   // [B,S,E]
    const float* w_qkv = (const float*)d_in[1];   // [3E,E]
    const float* b_qkv = (const float*)d_in[2];   // [3E]
    const float* w_out = (const float*)d_in[3];   // [E,E]
    const float* b_out = (const float*)d_in[4];   // [E]
    float* out = (float*)d_out;                   // [B,S,E]

    cudaFuncSetAttribute(attn_tc, cudaFuncAttributeMaxDynamicSharedMemorySize,
                         ATTN_SMEM_BYTES);
    cudaFuncSetAttribute(gemm_tc4<0>, cudaFuncAttributeMaxDynamicSharedMemorySize,
                         GEMM_SMEM);
    cudaFuncSetAttribute(gemm_tc4<1>, cudaFuncAttributeMaxDynamicSharedMemorySize,
                         GEMM_SMEM);

    // 0. split inputs/weights to bf16 hi/lo
    cvt_inputs<<<8192, 256>>>(x, w_qkv, w_out);

    // 1. QKV projection + head split (2-stage pipelined TC gemm, 2 CTAs/SM)
    gemm_tc4<0><<<dim3((3*EMBED)/128, MROWS/128), 256, GEMM_SMEM>>>(
        b_qkv, nullptr, MROWS, 3*EMBED, EMBED);

    // 2. Causal flash attention (TC, split-bf16) -> split ctx
    attn_tc<<<dim3(SEQ/128, BATCH*NHEADS), 256, ATTN_SMEM_BYTES>>>();

    // 3. Output projection (2-stage pipelined TC gemm, 2 CTAs/SM)
    gemm_tc4<1><<<dim3(EMBED/128, MROWS/128), 256, GEMM_SMEM>>>(
        b_out, out, MROWS, EMBED, EMBED);
}

// round 11
// speedup vs baseline: 1.3670x; 1.3670x over previous
#include <cuda_runtime.h>
#include <cuda_bf16.h>
#include <cstdint>

#define EMBED   1024
#define NHEADS  16
#define HDIM    64
#define BATCH   2
#define SEQ     2048
#define MROWS   (BATCH*SEQ)   // 4096

#define NEG_INF (-1e30f)

typedef __nv_bfloat16 bf;

// tcgen05 is NOT usable (harness emits compute_103; ptxas rejects tcgen05.*).
// All tensor work via mma.sync (HMMA) + split-bf16 (3 MMAs ~ fp32 accuracy).

// ---------------------------------------------------------------------------
// Scratch (device globals). Everything bf16 hi/lo.
// ---------------------------------------------------------------------------
__device__ bf g_Xh[(size_t)MROWS*EMBED],   g_Xl[(size_t)MROWS*EMBED];
__device__ bf g_Wqh[(size_t)3*EMBED*EMBED], g_Wql[(size_t)3*EMBED*EMBED];
__device__ bf g_Woh[(size_t)EMBED*EMBED],  g_Wol[(size_t)EMBED*EMBED];
__device__ bf g_Qh[(size_t)MROWS*EMBED],   g_Ql[(size_t)MROWS*EMBED];
__device__ bf g_Kh[(size_t)MROWS*EMBED],   g_Kl[(size_t)MROWS*EMBED];
__device__ bf g_Vh[(size_t)MROWS*EMBED],   g_Vl[(size_t)MROWS*EMBED];
__device__ bf g_Ch[(size_t)MROWS*EMBED],   g_Cl[(size_t)MROWS*EMBED];

// ---------------------------------------------------------------------------
// PTX helpers
// ---------------------------------------------------------------------------
__device__ __forceinline__ uint32_t saddr(const void* p) {
    return (uint32_t)__cvta_generic_to_shared(p);
}
__device__ __forceinline__ void cpa16(uint32_t dst, const void* src) {
    asm volatile("cp.async.cg.shared.global [%0], [%1], 16;\n" :: "r"(dst), "l"(src));
}
__device__ __forceinline__ void cpa_commit() {
    asm volatile("cp.async.commit_group;\n");
}
template<int N>
__device__ __forceinline__ void cpa_wait() {
    asm volatile("cp.async.wait_group %0;\n" :: "n"(N));
}
__device__ __forceinline__ void ldsm_x4(uint32_t& r0, uint32_t& r1,
                                        uint32_t& r2, uint32_t& r3, uint32_t a) {
    asm volatile("ldmatrix.sync.aligned.m8n8.x4.shared.b16 {%0,%1,%2,%3}, [%4];"
                 : "=r"(r0), "=r"(r1), "=r"(r2), "=r"(r3) : "r"(a));
}
__device__ __forceinline__ void ldsm_x4_t(uint32_t& r0, uint32_t& r1,
                                          uint32_t& r2, uint32_t& r3, uint32_t a) {
    asm volatile("ldmatrix.sync.aligned.m8n8.x4.trans.shared.b16 {%0,%1,%2,%3}, [%4];"
                 : "=r"(r0), "=r"(r1), "=r"(r2), "=r"(r3) : "r"(a));
}
__device__ __forceinline__ void mma_bf16(float* c, const uint32_t* a, const uint32_t* b) {
    asm volatile(
        "mma.sync.aligned.m16n8k16.row.col.f32.bf16.bf16.f32 "
        "{%0,%1,%2,%3}, {%4,%5,%6,%7}, {%8,%9}, {%0,%1,%2,%3};"
        : "+f"(c[0]), "+f"(c[1]), "+f"(c[2]), "+f"(c[3])
        : "r"(a[0]), "r"(a[1]), "r"(a[2]), "r"(a[3]), "r"(b[0]), "r"(b[1]));
}
__device__ __forceinline__ uint32_t pk(bf a, bf b) {
    return (uint32_t)__bfloat16_as_ushort(a) | ((uint32_t)__bfloat16_as_ushort(b) << 16);
}
__device__ __forceinline__ void split_pack(float a, float b, uint32_t& hi, uint32_t& lo) {
    bf ah = __float2bfloat16(a), bh = __float2bfloat16(b);
    hi = pk(ah, bh);
    lo = pk(__float2bfloat16(a - __bfloat162float(ah)),
            __float2bfloat16(b - __bfloat162float(bh)));
}
__device__ __forceinline__ void cvt_store4(float4 f, bf* hp, bf* lp) {
    uint32_t h0, l0, h1, l1;
    split_pack(f.x, f.y, h0, l0);
    split_pack(f.z, f.w, h1, l1);
    uint2 hv; hv.x = h0; hv.y = h1;
    uint2 lv; lv.x = l0; lv.y = l1;
    *(uint2*)hp = hv;
    *(uint2*)lp = lv;
}

// ---------------------------------------------------------------------------
// Input conversion pre-pass.
// ---------------------------------------------------------------------------
__global__ __launch_bounds__(256)
void cvt_inputs(const float* __restrict__ x, const float* __restrict__ wq,
                const float* __restrict__ wo)
{
    const int i = blockIdx.x * 256 + threadIdx.x;
    const float* src; bf *dh, *dl; int off;
    if (i < 1048576)            { src = x;  dh = g_Xh;  dl = g_Xl;  off = i; }
    else if (i < 1048576+786432){ src = wq; dh = g_Wqh; dl = g_Wql; off = i - 1048576; }
    else                        { src = wo; dh = g_Woh; dl = g_Wol; off = i - 1835008; }
    float4 f = ((const float4*)src)[off];
    cvt_store4(f, dh + (size_t)off*4, dl + (size_t)off*4);
}

// ---------------------------------------------------------------------------
// Pipelined HMMA GEMM (split-bf16), HIGH-INTENSITY warp tiles.
// 256 threads, CTA tile 128x256, 8 warps (2m x 4n), warp tile 64x64.
// Per k16: A 4KB + B 4KB smem reads feed 96 HMMA -> 48 FLOP/B (smem no
// longer binding; was 16.4 FLOP/B at warp 64x32 -> 46% tensor ceiling).
// K-step 32, 2-stage cp.async, 1 CTA/SM, <=255 regs (launch_bounds(256,1)).
// Stage layout (80B rows): Ah 0 (10240), Al 10240, Bh 20480 (20480), Bl 40960.
// Stage stride 61440; 2 stages = 122880 B.
// MODE 0: A=g_X, B=g_Wq, epilogue scatters split Q/K/V.
// MODE 1: A=g_C, B=g_Wo, epilogue fp32 C.
// ---------------------------------------------------------------------------
#define GSTAGE_B  61440
#define GEMM_SMEM (2*GSTAGE_B)   // 122880

template<int MODE>
__global__ __launch_bounds__(256, 1)
void gemm_tc5(const float* __restrict__ bias, float* __restrict__ C,
              int M, int N, int K)
{
    extern __shared__ bf sm[];
    const uint32_t smem0 = saddr(sm);

    const bf* Ahp = (MODE == 0) ? g_Xh : g_Ch;
    const bf* Alp = (MODE == 0) ? g_Xl : g_Cl;
    const bf* Bhp = (MODE == 0) ? g_Wqh : g_Woh;
    const bf* Blp = (MODE == 0) ? g_Wql : g_Wol;

    const int tid  = threadIdx.x;
    const int lane = tid & 31;
    const int warp = tid >> 5;
    const int wm   = warp >> 2;   // 0..1
    const int wn   = warp & 3;    // 0..3
    const int bm   = blockIdx.y * 128;
    const int bn   = blockIdx.x * 256;

    // ---- loaders ----
    // A: 128 rows x 64B -> 2x16B chunks per thread (hi and lo)
    const int alr = tid >> 1;
    const int ac  = (tid & 1) * 32;          // byte offset in 64B row
    // B: 256 rows x 64B -> row per thread, 4x16B chunks (hi and lo)
    const bf* aH = Ahp + (size_t)(bm + alr) * K + ac/2;
    const bf* aL = Alp + (size_t)(bm + alr) * K + ac/2;
    const bf* bH = Bhp + (size_t)(bn + tid) * K;
    const bf* bL = Blp + (size_t)(bn + tid) * K;
    const uint32_t adst = smem0 + alr*80 + ac;
    const uint32_t bdst = smem0 + 20480 + tid*80;

    const int nsteps = K >> 5;

    auto copy_stage = [&](int k0, int stg) {
        const uint32_t s = stg * GSTAGE_B;
        cpa16(adst + s,          aH + k0);  cpa16(adst + s + 16,         aH + k0 + 8);
        cpa16(adst + s + 10240,  aL + k0);  cpa16(adst + s + 10240 + 16, aL + k0 + 8);
        #pragma unroll
        for (int j = 0; j < 4; j++) {
            cpa16(bdst + s         + j*16, bH + k0 + j*8);
            cpa16(bdst + s + 20480 + j*16, bL + k0 + j*8);
        }
    };

    float acc[4][8][4];   // [m16 tile][n8 tile][frag] = 128 regs
    #pragma unroll
    for (int t = 0; t < 4; t++)
        #pragma unroll
        for (int n = 0; n < 8; n++)
            #pragma unroll
            for (int e = 0; e < 4; e++) acc[t][n][e] = 0.f;

    const int arow  = wm*64 + (lane & 15);
    const int acol  = ((lane >> 4) & 1) * 8;
    const int brofs = (lane & 7) + ((lane >> 4) & 1) * 8;
    const int bcol  = ((lane >> 3) & 1) * 8;
    const uint32_t aoff = (uint32_t)(arow*80 + acol*2);

    copy_stage(0, 0);  cpa_commit();

    for (int ks = 0; ks < nsteps; ks++) {
        const int nk = ks + 1;
        if (nk < nsteps) copy_stage(nk*32, nk & 1);
        cpa_commit();
        cpa_wait<1>();
        __syncthreads();

        const uint32_t base = smem0 + (ks & 1) * GSTAGE_B;

        #pragma unroll
        for (int kk = 0; kk < 2; kk++) {
            // A fragments for all 4 m16 tiles (reused across both B halves)
            uint32_t ah[4][4], al[4][4];
            const uint32_t ab = base + aoff + kk*32;
            #pragma unroll
            for (int t = 0; t < 4; t++) {
                ldsm_x4(ah[t][0], ah[t][1], ah[t][2], ah[t][3], ab + t*1280);
                ldsm_x4(al[t][0], al[t][1], al[t][2], al[t][3], ab + 10240 + t*1280);
            }
            #pragma unroll
            for (int h = 0; h < 2; h++) {
                uint32_t bh[2][4], bl[2][4];
                const uint32_t bbx = base + 20480 +
                    (uint32_t)((wn*64 + h*32 + brofs)*80 + bcol*2) + kk*32;
                #pragma unroll
                for (int p = 0; p < 2; p++) {
                    ldsm_x4(bh[p][0], bh[p][1], bh[p][2], bh[p][3], bbx + p*1280);
                    ldsm_x4(bl[p][0], bl[p][1], bl[p][2], bl[p][3], bbx + 20480 + p*1280);
                }
                #pragma unroll
                for (int t = 0; t < 4; t++) {
                    // term-outer, n-inner: same-acc reuse spaced by 4 HMMAs
                    #pragma unroll
                    for (int n = 0; n < 4; n++)
                        mma_bf16(acc[t][h*4 + n], ah[t], &bh[n >> 1][(n & 1) * 2]);
                    #pragma unroll
                    for (int n = 0; n < 4; n++)
                        mma_bf16(acc[t][h*4 + n], ah[t], &bl[n >> 1][(n & 1) * 2]);
                    #pragma unroll
                    for (int n = 0; n < 4; n++)
                        mma_bf16(acc[t][h*4 + n], al[t], &bh[n >> 1][(n & 1) * 2]);
                }
            }
        }
        __syncthreads();
    }

    // ---- epilogue ----
    #pragma unroll
    for (int t = 0; t < 4; t++) {
        const int r0 = bm + wm*64 + t*16 + (lane >> 2);
        #pragma unroll
        for (int n = 0; n < 8; n++) {
            const int col = bn + wn*64 + n*8 + (lane & 3)*2;
            const float b0v = bias[col], b1v = bias[col + 1];
            const float* c = acc[t][n];
            if (MODE == 0) {
                const int sel = col >> 10;      // 0=Q 1=K 2=V
                const int e   = col & 1023;
                bf* ph = (sel == 0) ? g_Qh : (sel == 1) ? g_Kh : g_Vh;
                bf* pl = (sel == 0) ? g_Ql : (sel == 1) ? g_Kl : g_Vl;
                const int hh = e >> 6, dd = e & 63;
                #pragma unroll
                for (int rr = 0; rr < 2; rr++) {
                    const int row = r0 + rr*8;
                    const int bbv = row >> 11, ss = row & 2047;
                    const size_t idx = (((size_t)(bbv*NHEADS + hh))*SEQ + ss)*HDIM + dd;
                    uint32_t hi, lo;
                    split_pack(c[rr*2] + b0v, c[rr*2+1] + b1v, hi, lo);
                    *(uint32_t*)&ph[idx] = hi;
                    *(uint32_t*)&pl[idx] = lo;
                }
            } else {
                float2 v0; v0.x = c[0] + b0v; v0.y = c[1] + b1v;
                float2 v1; v1.x = c[2] + b0v; v1.y = c[3] + b1v;
                *(float2*)&C[(size_t)r0       * N + col] = v0;
                *(float2*)&C[(size_t)(r0 + 8) * N + col] = v1;
            }
        }
    }
}

// ---------------------------------------------------------------------------
// Tensor-core flash attention (causal), split-bf16, cp.async loads.
// (unchanged — proven 593.9us configuration)
// ---------------------------------------------------------------------------
#define ATTN_SMEM_BYTES 73728

__global__ __launch_bounds__(256, 1)
void attn_tc()
{
    extern __shared__ bf sb[];
    bf (*Qh)[72] = (bf(*)[72])(sb);
    bf (*Ql)[72] = (bf(*)[72])(sb + 9216);
    bf (*Kh)[72] = (bf(*)[72])(sb + 18432);
    bf (*Kl)[72] = (bf(*)[72])(sb + 23040);
    bf (*Vh)[72] = (bf(*)[72])(sb + 27648);
    bf (*Vl)[72] = (bf(*)[72])(sb + 32256);

    const int qt   = (int)(gridDim.x - 1) - (int)blockIdx.x;
    const int bhid = blockIdx.y;
    const int bb   = bhid / NHEADS;
    const int hh   = bhid % NHEADS;

    const size_t hb = (size_t)bhid * SEQ * HDIM;

    const int tid  = threadIdx.x;
    const int lane = tid & 31;
    const int w    = tid >> 5;
    const int qbase = qt * 128;

    {
        const int lr = tid >> 1, hf = tid & 1;
        const bf* qh = g_Qh + hb + (size_t)(qbase + lr)*HDIM + hf*32;
        const bf* ql = g_Ql + hb + (size_t)(qbase + lr)*HDIM + hf*32;
        const uint32_t dh = saddr(&Qh[lr][hf*32]);
        const uint32_t dl = saddr(&Ql[lr][hf*32]);
        #pragma unroll
        for (int u = 0; u < 4; u++) {
            cpa16(dh + u*16, qh + u*8);
            cpa16(dl + u*16, ql + u*8);
        }
        cpa_commit();
        cpa_wait<0>();
    }
    __syncthreads();

    uint32_t qfh[4][4], qfl[4][4];
    {
        const int arow = w*16 + (lane & 15);
        const int acol = ((lane >> 4) & 1) * 8;
        #pragma unroll
        for (int kc = 0; kc < 4; kc++) {
            ldsm_x4(qfh[kc][0], qfh[kc][1], qfh[kc][2], qfh[kc][3],
                    saddr(&Qh[arow][kc*16 + acol]));
            ldsm_x4(qfl[kc][0], qfl[kc][1], qfl[kc][2], qfl[kc][3],
                    saddr(&Ql[arow][kc*16 + acol]));
        }
    }

    float O[8][4];
    #pragma unroll
    for (int nt = 0; nt < 8; nt++)
        #pragma unroll
        for (int e = 0; e < 4; e++) O[nt][e] = 0.f;

    float m0 = NEG_INF, m1 = NEG_INF, l0 = 0.f, l1 = 0.f;
    const int r0g = qbase + w*16 + (lane >> 2);
    const int r1g = r0g + 8;
    const int wr  = qbase + w*16;

    const int krow = (lane & 7) + ((lane >> 4) & 1) * 8;
    const int kcol = ((lane >> 3) & 1) * 8;
    const int vrow = (lane & 7) + ((lane >> 3) & 1) * 8;
    const int vcol = ((lane >> 4) & 1) * 8;

    const int kr = tid >> 2, q4 = tid & 3;

    const int nktiles = 2*qt + 2;
    for (int kt = 0; kt < nktiles; kt++) {
        const int kbase = kt * 64;
        __syncthreads();

        {
            const size_t srcoff = hb + (size_t)(kbase + kr)*HDIM + q4*16;
            const uint32_t doff = (uint32_t)(kr*144 + q4*32);
            const uint32_t kh = saddr(Kh) + doff, kl = saddr(Kl) + doff;
            const uint32_t vh = saddr(Vh) + doff, vl = saddr(Vl) + doff;
            cpa16(kh, g_Kh + srcoff);  cpa16(kh + 16, g_Kh + srcoff + 8);
            cpa16(kl, g_Kl + srcoff);  cpa16(kl + 16, g_Kl + srcoff + 8);
            cpa16(vh, g_Vh + srcoff);  cpa16(vh + 16, g_Vh + srcoff + 8);
            cpa16(vl, g_Vl + srcoff);  cpa16(vl + 16, g_Vl + srcoff + 8);
            cpa_commit();
            cpa_wait<0>();
        }
        __syncthreads();

        if (wr + 15 < kbase) continue;

        float s[8][4];
        #pragma unroll
        for (int nt = 0; nt < 8; nt++)
            #pragma unroll
            for (int e = 0; e < 4; e++) s[nt][e] = 0.f;

        #pragma unroll
        for (int kc = 0; kc < 4; kc++) {
            uint32_t kh4[4][4], kl4[4][4];
            #pragma unroll
            for (int p = 0; p < 4; p++) {
                ldsm_x4(kh4[p][0], kh4[p][1], kh4[p][2], kh4[p][3],
                        saddr(&Kh[p*16 + krow][kc*16 + kcol]));
                ldsm_x4(kl4[p][0], kl4[p][1], kl4[p][2], kl4[p][3],
                        saddr(&Kl[p*16 + krow][kc*16 + kcol]));
            }
            #pragma unroll
            for (int nt = 0; nt < 8; nt++) {
                const uint32_t* Bhf = &kh4[nt >> 1][(nt & 1) * 2];
                const uint32_t* Blf = &kl4[nt >> 1][(nt & 1) * 2];
                mma_bf16(s[nt], qfh[kc], Bhf);
                mma_bf16(s[nt], qfh[kc], Blf);
                mma_bf16(s[nt], qfl[kc], Bhf);
            }
        }

        #pragma unroll
        for (int nt = 0; nt < 8; nt++)
            #pragma unroll
            for (int e = 0; e < 4; e++) s[nt][e] *= 0.125f;

        if (kbase + 63 > wr) {
            #pragma unroll
            for (int nt = 0; nt < 8; nt++) {
                const int c0 = kbase + nt*8 + ((lane & 3) << 1);
                if (c0     > r0g) s[nt][0] = NEG_INF;
                if (c0 + 1 > r0g) s[nt][1] = NEG_INF;
                if (c0     > r1g) s[nt][2] = NEG_INF;
                if (c0 + 1 > r1g) s[nt][3] = NEG_INF;
            }
        }

        float mx0 = NEG_INF, mx1 = NEG_INF;
        #pragma unroll
        for (int nt = 0; nt < 8; nt++) {
            mx0 = fmaxf(mx0, fmaxf(s[nt][0], s[nt][1]));
            mx1 = fmaxf(mx1, fmaxf(s[nt][2], s[nt][3]));
        }
        mx0 = fmaxf(mx0, __shfl_xor_sync(0xffffffffu, mx0, 1));
        mx0 = fmaxf(mx0, __shfl_xor_sync(0xffffffffu, mx0, 2));
        mx1 = fmaxf(mx1, __shfl_xor_sync(0xffffffffu, mx1, 1));
        mx1 = fmaxf(mx1, __shfl_xor_sync(0xffffffffu, mx1, 2));

        const float nm0 = fmaxf(m0, mx0);
        const float nm1 = fmaxf(m1, mx1);
        const float f0 = __expf(m0 - nm0);
        const float f1 = __expf(m1 - nm1);

        float ps0 = 0.f, ps1 = 0.f;
        #pragma unroll
        for (int nt = 0; nt < 8; nt++) {
            s[nt][0] = __expf(s[nt][0] - nm0);
            s[nt][1] = __expf(s[nt][1] - nm0);
            s[nt][2] = __expf(s[nt][2] - nm1);
            s[nt][3] = __expf(s[nt][3] - nm1);
            ps0 += s[nt][0] + s[nt][1];
            ps1 += s[nt][2] + s[nt][3];
        }
        ps0 += __shfl_xor_sync(0xffffffffu, ps0, 1);
        ps0 += __shfl_xor_sync(0xffffffffu, ps0, 2);
        ps1 += __shfl_xor_sync(0xffffffffu, ps1, 1);
        ps1 += __shfl_xor_sync(0xffffffffu, ps1, 2);

        l0 = l0 * f0 + ps0;  m0 = nm0;
        l1 = l1 * f1 + ps1;  m1 = nm1;

        #pragma unroll
        for (int nt = 0; nt < 8; nt++) {
            O[nt][0] *= f0; O[nt][1] *= f0;
            O[nt][2] *= f1; O[nt][3] *= f1;
        }

        #pragma unroll
        for (int kc = 0; kc < 4; kc++) {
            uint32_t pah[4], pal[4];
            split_pack(s[2*kc  ][0], s[2*kc  ][1], pah[0], pal[0]);
            split_pack(s[2*kc  ][2], s[2*kc  ][3], pah[1], pal[1]);
            split_pack(s[2*kc+1][0], s[2*kc+1][1], pah[2], pal[2]);
            split_pack(s[2*kc+1][2], s[2*kc+1][3], pah[3], pal[3]);

            uint32_t vh4[4][4], vl4[4][4];
            #pragma unroll
            for (int p = 0; p < 4; p++) {
                ldsm_x4_t(vh4[p][0], vh4[p][1], vh4[p][2], vh4[p][3],
                          saddr(&Vh[kc*16 + vrow][p*16 + vcol]));
                ldsm_x4_t(vl4[p][0], vl4[p][1], vl4[p][2], vl4[p][3],
                          saddr(&Vl[kc*16 + vrow][p*16 + vcol]));
            }
            #pragma unroll
            for (int nt = 0; nt < 8; nt++) {
                const uint32_t* Bvh = &vh4[nt >> 1][(nt & 1) * 2];
                const uint32_t* Bvl = &vl4[nt >> 1][(nt & 1) * 2];
                mma_bf16(O[nt], pah, Bvh);
                mma_bf16(O[nt], pah, Bvl);
                mma_bf16(O[nt], pal, Bvh);
            }
        }
    }

    const float inv0 = 1.f / l0;
    const float inv1 = 1.f / l1;
    const size_t i0 = ((size_t)bb*SEQ + r0g)*EMBED + hh*HDIM;
    const size_t i1 = ((size_t)bb*SEQ + r1g)*EMBED + hh*HDIM;
    #pragma unroll
    for (int nt = 0; nt < 8; nt++) {
        const int c = nt*8 + (lane & 3)*2;
        uint32_t hi, lo;
        split_pack(O[nt][0]*inv0, O[nt][1]*inv0, hi, lo);
        *(uint32_t*)&g_Ch[i0 + c] = hi;
        *(uint32_t*)&g_Cl[i0 + c] = lo;
        split_pack(O[nt][2]*inv1, O[nt][3]*inv1, hi, lo);
        *(uint32_t*)&g_Ch[i1 + c] = hi;
        *(uint32_t*)&g_Cl[i1 + c] = lo;
    }
}

// ---------------------------------------------------------------------------
extern "C" void kernel_launch(void* const* d_in, const int* in_sizes, int n_in,
                              void* d_out, int out_size)
{
    const float* x     = (const float*)d_in[0];   // [B,S,E]
    const float* w_qkv = (const float*)d_in[1];   // [3E,E]
    const float* b_qkv = (const float*)d_in[2];   // [3E]
    const float* w_out = (const float*)d_in[3];   // [E,E]
    const float* b_out = (const float*)d_in[4];   // [E]
    float* out = (float*)d_out;                   // [B,S,E]

    cudaFuncSetAttribute(attn_tc, cudaFuncAttributeMaxDynamicSharedMemorySize,
                         ATTN_SMEM_BYTES);
    cudaFuncSetAttribute(gemm_tc5<0>, cudaFuncAttributeMaxDynamicSharedMemorySize,
                         GEMM_SMEM);
    cudaFuncSetAttribute(gemm_tc5<1>, cudaFuncAttributeMaxDynamicSharedMemorySize,
                         GEMM_SMEM);

    // 0. split inputs/weights to bf16 hi/lo
    cvt_inputs<<<8192, 256>>>(x, w_qkv, w_out);

    // 1. QKV projection + head split (warp-64x64 pipelined HMMA gemm)
    gemm_tc5<0><<<dim3((3*EMBED)/256, MROWS/128), 256, GEMM_SMEM>>>(
        b_qkv, nullptr, MROWS, 3*EMBED, EMBED);

    // 2. Causal flash attention (TC, split-bf16) -> split ctx
    attn_tc<<<dim3(SEQ/128, BATCH*NHEADS), 256, ATTN_SMEM_BYTES>>>();

    // 3. Output projection (warp-64x64 pipelined HMMA gemm)
    gemm_tc5<1><<<dim3(EMBED/256, MROWS/128), 256, GEMM_SMEM>>>(
        b_out, out, MROWS, EMBED, EMBED);
}

// round 12
// speedup vs baseline: 3.1778x; 2.3247x over previous
#include <cuda_runtime.h>
#include <cuda_fp16.h>
#include <cstdint>

#define EMBED   1024
#define NHEADS  16
#define HDIM    64
#define BATCH   2
#define SEQ     2048
#define MROWS   (BATCH*SEQ)   // 4096

#define NEG_INF (-1e30f)

typedef __half fh;

// tcgen05 is NOT usable (harness emits compute_103 PTX; ptxas rejects it).
// All tensor work via mma.sync HMMA. Pure fp16 operands + fp32 accumulate:
// 1 MMA per logical MMA (vs 3-term split-bf16). Predicted rel_err ~4-6e-4
// (11-bit mantissa roundings, ~5 independent 2^-12 contributions) < 1e-3.

// ---------------------------------------------------------------------------
// Scratch (device globals). Everything single fp16.
// ---------------------------------------------------------------------------
__device__ fh g_X[(size_t)MROWS*EMBED];
__device__ fh g_Wq[(size_t)3*EMBED*EMBED];
__device__ fh g_Wo[(size_t)EMBED*EMBED];
__device__ fh g_Q[(size_t)MROWS*EMBED];
__device__ fh g_K[(size_t)MROWS*EMBED];
__device__ fh g_V[(size_t)MROWS*EMBED];
__device__ fh g_C[(size_t)MROWS*EMBED];

// ---------------------------------------------------------------------------
// PTX helpers
// ---------------------------------------------------------------------------
__device__ __forceinline__ uint32_t saddr(const void* p) {
    return (uint32_t)__cvta_generic_to_shared(p);
}
__device__ __forceinline__ void cpa16(uint32_t dst, const void* src) {
    asm volatile("cp.async.cg.shared.global [%0], [%1], 16;\n" :: "r"(dst), "l"(src));
}
__device__ __forceinline__ void cpa_commit() {
    asm volatile("cp.async.commit_group;\n");
}
template<int N>
__device__ __forceinline__ void cpa_wait() {
    asm volatile("cp.async.wait_group %0;\n" :: "n"(N));
}
__device__ __forceinline__ void ldsm_x4(uint32_t& r0, uint32_t& r1,
                                        uint32_t& r2, uint32_t& r3, uint32_t a) {
    asm volatile("ldmatrix.sync.aligned.m8n8.x4.shared.b16 {%0,%1,%2,%3}, [%4];"
                 : "=r"(r0), "=r"(r1), "=r"(r2), "=r"(r3) : "r"(a));
}
__device__ __forceinline__ void ldsm_x4_t(uint32_t& r0, uint32_t& r1,
                                          uint32_t& r2, uint32_t& r3, uint32_t a) {
    asm volatile("ldmatrix.sync.aligned.m8n8.x4.trans.shared.b16 {%0,%1,%2,%3}, [%4];"
                 : "=r"(r0), "=r"(r1), "=r"(r2), "=r"(r3) : "r"(a));
}
__device__ __forceinline__ void mma_f16(float* c, const uint32_t* a, const uint32_t* b) {
    asm volatile(
        "mma.sync.aligned.m16n8k16.row.col.f32.f16.f16.f32 "
        "{%0,%1,%2,%3}, {%4,%5,%6,%7}, {%8,%9}, {%0,%1,%2,%3};"
        : "+f"(c[0]), "+f"(c[1]), "+f"(c[2]), "+f"(c[3])
        : "r"(a[0]), "r"(a[1]), "r"(a[2]), "r"(a[3]), "r"(b[0]), "r"(b[1]));
}
__device__ __forceinline__ uint32_t packh2(float a, float b) {
    __half2 h = __floats2half2_rn(a, b);   // a -> low half
    return *(uint32_t*)&h;
}

// ---------------------------------------------------------------------------
// Input conversion pre-pass: x, w_qkv, w_out -> fp16 globals.
// 2097152 float4 units total (X 1048576, Wq 786432, Wo 262144).
// ---------------------------------------------------------------------------
__global__ __launch_bounds__(256)
void cvt_inputs(const float* __restrict__ x, const float* __restrict__ wq,
                const float* __restrict__ wo)
{
    const int i = blockIdx.x * 256 + threadIdx.x;
    const float* src; fh* dst; int off;
    if (i < 1048576)            { src = x;  dst = g_X;  off = i; }
    else if (i < 1048576+786432){ src = wq; dst = g_Wq; off = i - 1048576; }
    else                        { src = wo; dst = g_Wo; off = i - 1835008; }
    float4 f = ((const float4*)src)[off];
    uint2 v; v.x = packh2(f.x, f.y); v.y = packh2(f.z, f.w);
    *(uint2*)(dst + (size_t)off*4) = v;
}

// ---------------------------------------------------------------------------
// Pipelined fp16 HMMA GEMM: out = A @ Bw^T + bias
// 256 threads, CTA tile 128x128, 8 warps (2m x 4n), warp tile 64x32.
// K-step 32, 2-stage cp.async, 2 CTAs/SM. 1 MMA per logical MMA.
// Stage layout (80B rows): A 0 (10240 B), B 10240 (10240 B); stage 20480.
// MODE 0: A=g_X, B=g_Wq, epilogue scatters fp16 Q/K/V ([B,H,S,D]).
// MODE 1: A=g_C, B=g_Wo, epilogue fp32 C.
// ---------------------------------------------------------------------------
#define GSTAGE_B  20480
#define GEMM_SMEM (2*GSTAGE_B)   // 40960

template<int MODE>
__global__ __launch_bounds__(256, 2)
void gemm_h(const float* __restrict__ bias, float* __restrict__ C,
            int M, int N, int K)
{
    extern __shared__ fh sm[];
    const uint32_t smem0 = saddr(sm);

    const fh* Ap = (MODE == 0) ? g_X : g_C;
    const fh* Bp = (MODE == 0) ? g_Wq : g_Wo;

    const int tid  = threadIdx.x;
    const int lane = tid & 31;
    const int warp = tid >> 5;
    const int wm   = warp >> 2;
    const int wn   = warp & 3;
    const int bm   = blockIdx.y * 128;
    const int bn   = blockIdx.x * 128;

    const int lr    = tid >> 1;
    const int half_ = tid & 1;

    const fh* aP = Ap + (size_t)(bm + lr) * K + half_*16;
    const fh* bP = Bp + (size_t)(bn + lr) * K + half_*16;
    const uint32_t adst = smem0 + lr*80 + half_*32;
    const uint32_t bdst = adst + 10240;

    const int nsteps = K >> 5;

    auto copy_stage = [&](int k0, int stg) {
        const uint32_t d = stg * GSTAGE_B;
        cpa16(adst + d,      aP + k0);  cpa16(adst + d + 16, aP + k0 + 8);
        cpa16(bdst + d,      bP + k0);  cpa16(bdst + d + 16, bP + k0 + 8);
    };

    float acc[16][4];
    #pragma unroll
    for (int i = 0; i < 16; i++)
        #pragma unroll
        for (int j = 0; j < 4; j++) acc[i][j] = 0.f;

    const int arow = wm*64 + (lane & 15);
    const int acol = ((lane >> 4) & 1) * 8;
    const int brow = wn*32 + (lane & 7) + ((lane >> 4) & 1) * 8;
    const int bcol = ((lane >> 3) & 1) * 8;
    const uint32_t aoff = (uint32_t)(arow*80 + acol*2);
    const uint32_t boff = (uint32_t)(10240 + brow*80 + bcol*2);

    copy_stage(0, 0);  cpa_commit();

    for (int ks = 0; ks < nsteps; ks++) {
        const int nk = ks + 1;
        if (nk < nsteps) copy_stage(nk*32, nk & 1);
        cpa_commit();
        cpa_wait<1>();
        __syncthreads();

        const uint32_t base = smem0 + (ks & 1) * GSTAGE_B;

        #pragma unroll
        for (int kk = 0; kk < 2; kk++) {
            const uint32_t ab  = base + aoff + kk*32;
            const uint32_t bbx = base + boff + kk*32;
            uint32_t bh[2][4];
            #pragma unroll
            for (int p = 0; p < 2; p++)
                ldsm_x4(bh[p][0], bh[p][1], bh[p][2], bh[p][3], bbx + p*1280);
            #pragma unroll
            for (int t = 0; t < 4; t++) {
                uint32_t ah[4];
                ldsm_x4(ah[0], ah[1], ah[2], ah[3], ab + t*1280);
                #pragma unroll
                for (int n = 0; n < 4; n++)
                    mma_f16(acc[t*4 + n], ah, &bh[n >> 1][(n & 1) * 2]);
            }
        }
        __syncthreads();
    }

    // epilogue
    #pragma unroll
    for (int t = 0; t < 4; t++) {
        const int r0 = bm + wm*64 + t*16 + (lane >> 2);
        #pragma unroll
        for (int n = 0; n < 4; n++) {
            const int col = bn + wn*32 + n*8 + (lane & 3)*2;
            const float b0v = bias[col], b1v = bias[col + 1];
            const float* c = acc[t*4 + n];
            if (MODE == 0) {
                const int sel = col >> 10;      // 0=Q 1=K 2=V
                const int e   = col & 1023;
                fh* pq = (sel == 0) ? g_Q : (sel == 1) ? g_K : g_V;
                const int hh = e >> 6, dd = e & 63;
                #pragma unroll
                for (int rr = 0; rr < 2; rr++) {
                    const int row = r0 + rr*8;
                    const int bbv = row >> 11, ss = row & 2047;
                    const size_t idx = (((size_t)(bbv*NHEADS + hh))*SEQ + ss)*HDIM + dd;
                    *(uint32_t*)&pq[idx] = packh2(c[rr*2] + b0v, c[rr*2+1] + b1v);
                }
            } else {
                float2 v0; v0.x = c[0] + b0v; v0.y = c[1] + b1v;
                float2 v1; v1.x = c[2] + b0v; v1.y = c[3] + b1v;
                *(float2*)&C[(size_t)r0       * N + col] = v0;
                *(float2*)&C[(size_t)(r0 + 8) * N + col] = v1;
            }
        }
    }
}

// ---------------------------------------------------------------------------
// fp16 flash attention (causal), fp32 accumulators, cp.async loads.
// q-tile 128, k-tile 64, 8 warps (one m16 row-slab each). 1 MMA per logical.
// smem (halves): Q [128][72] @0, K [64][72] @9216, V [64][72] @13824.
// ---------------------------------------------------------------------------
#define ATTN_SMEM_BYTES 36864

__global__ __launch_bounds__(256, 1)
void attn_h()
{
    extern __shared__ fh sb[];
    fh (*Qs)[72] = (fh(*)[72])(sb);
    fh (*Ks)[72] = (fh(*)[72])(sb + 9216);
    fh (*Vs)[72] = (fh(*)[72])(sb + 13824);

    const int qt   = (int)(gridDim.x - 1) - (int)blockIdx.x;   // big tiles first
    const int bhid = blockIdx.y;
    const int bb   = bhid / NHEADS;
    const int hh   = bhid % NHEADS;

    const size_t hb = (size_t)bhid * SEQ * HDIM;

    const int tid  = threadIdx.x;
    const int lane = tid & 31;
    const int w    = tid >> 5;
    const int qbase = qt * 128;

    // ---- load Q tile (fp16 single) ----
    {
        const int lr = tid >> 1, hx = tid & 1;
        const fh* qsrc = g_Q + hb + (size_t)(qbase + lr)*HDIM + hx*32;
        const uint32_t dq = saddr(&Qs[lr][hx*32]);
        #pragma unroll
        for (int u = 0; u < 4; u++)
            cpa16(dq + u*16, qsrc + u*8);
        cpa_commit();
        cpa_wait<0>();
    }
    __syncthreads();

    // ---- Q fragments (registers for the whole kernel) ----
    uint32_t qf[4][4];
    {
        const int arow = w*16 + (lane & 15);
        const int acol = ((lane >> 4) & 1) * 8;
        #pragma unroll
        for (int kc = 0; kc < 4; kc++)
            ldsm_x4(qf[kc][0], qf[kc][1], qf[kc][2], qf[kc][3],
                    saddr(&Qs[arow][kc*16 + acol]));
    }

    float O[8][4];
    #pragma unroll
    for (int nt = 0; nt < 8; nt++)
        #pragma unroll
        for (int e = 0; e < 4; e++) O[nt][e] = 0.f;

    float m0 = NEG_INF, m1 = NEG_INF, l0 = 0.f, l1 = 0.f;
    const int r0g = qbase + w*16 + (lane >> 2);
    const int r1g = r0g + 8;
    const int wr  = qbase + w*16;

    const int krow = (lane & 7) + ((lane >> 4) & 1) * 8;
    const int kcol = ((lane >> 3) & 1) * 8;
    const int vrow = (lane & 7) + ((lane >> 3) & 1) * 8;
    const int vcol = ((lane >> 4) & 1) * 8;

    const int kr = tid >> 2, q4 = tid & 3;

    const int nktiles = 2*qt + 2;
    for (int kt = 0; kt < nktiles; kt++) {
        const int kbase = kt * 64;
        __syncthreads();   // all warps done reading K/V smem

        // ---- load K and V tiles (fp16 single) ----
        {
            const size_t srcoff = hb + (size_t)(kbase + kr)*HDIM + q4*16;
            const uint32_t doff = (uint32_t)(kr*144 + q4*32);
            const uint32_t dk = saddr(Ks) + doff;
            const uint32_t dv = saddr(Vs) + doff;
            cpa16(dk, g_K + srcoff);  cpa16(dk + 16, g_K + srcoff + 8);
            cpa16(dv, g_V + srcoff);  cpa16(dv + 16, g_V + srcoff + 8);
            cpa_commit();
            cpa_wait<0>();
        }
        __syncthreads();

        if (wr + 15 < kbase) continue;   // warp fully masked for this tile

        // ---- S = Q K^T ----
        float s[8][4];
        #pragma unroll
        for (int nt = 0; nt < 8; nt++)
            #pragma unroll
            for (int e = 0; e < 4; e++) s[nt][e] = 0.f;

        #pragma unroll
        for (int kc = 0; kc < 4; kc++) {
            uint32_t k4[4][4];
            #pragma unroll
            for (int p = 0; p < 4; p++)
                ldsm_x4(k4[p][0], k4[p][1], k4[p][2], k4[p][3],
                        saddr(&Ks[p*16 + krow][kc*16 + kcol]));
            #pragma unroll
            for (int nt = 0; nt < 8; nt++)
                mma_f16(s[nt], qf[kc], &k4[nt >> 1][(nt & 1) * 2]);
        }

        // scale + causal mask
        #pragma unroll
        for (int nt = 0; nt < 8; nt++)
            #pragma unroll
            for (int e = 0; e < 4; e++) s[nt][e] *= 0.125f;

        if (kbase + 63 > wr) {
            #pragma unroll
            for (int nt = 0; nt < 8; nt++) {
                const int c0 = kbase + nt*8 + ((lane & 3) << 1);
                if (c0     > r0g) s[nt][0] = NEG_INF;
                if (c0 + 1 > r0g) s[nt][1] = NEG_INF;
                if (c0     > r1g) s[nt][2] = NEG_INF;
                if (c0 + 1 > r1g) s[nt][3] = NEG_INF;
            }
        }

        // ---- online softmax ----
        float mx0 = NEG_INF, mx1 = NEG_INF;
        #pragma unroll
        for (int nt = 0; nt < 8; nt++) {
            mx0 = fmaxf(mx0, fmaxf(s[nt][0], s[nt][1]));
            mx1 = fmaxf(mx1, fmaxf(s[nt][2], s[nt][3]));
        }
        mx0 = fmaxf(mx0, __shfl_xor_sync(0xffffffffu, mx0, 1));
        mx0 = fmaxf(mx0, __shfl_xor_sync(0xffffffffu, mx0, 2));
        mx1 = fmaxf(mx1, __shfl_xor_sync(0xffffffffu, mx1, 1));
        mx1 = fmaxf(mx1, __shfl_xor_sync(0xffffffffu, mx1, 2));

        const float nm0 = fmaxf(m0, mx0);
        const float nm1 = fmaxf(m1, mx1);
        const float f0 = __expf(m0 - nm0);
        const float f1 = __expf(m1 - nm1);

        float ps0 = 0.f, ps1 = 0.f;
        #pragma unroll
        for (int nt = 0; nt < 8; nt++) {
            s[nt][0] = __expf(s[nt][0] - nm0);
            s[nt][1] = __expf(s[nt][1] - nm0);
            s[nt][2] = __expf(s[nt][2] - nm1);
            s[nt][3] = __expf(s[nt][3] - nm1);
            ps0 += s[nt][0] + s[nt][1];
            ps1 += s[nt][2] + s[nt][3];
        }
        ps0 += __shfl_xor_sync(0xffffffffu, ps0, 1);
        ps0 += __shfl_xor_sync(0xffffffffu, ps0, 2);
        ps1 += __shfl_xor_sync(0xffffffffu, ps1, 1);
        ps1 += __shfl_xor_sync(0xffffffffu, ps1, 2);

        l0 = l0 * f0 + ps0;  m0 = nm0;
        l1 = l1 * f1 + ps1;  m1 = nm1;

        #pragma unroll
        for (int nt = 0; nt < 8; nt++) {
            O[nt][0] *= f0; O[nt][1] *= f0;
            O[nt][2] *= f1; O[nt][3] *= f1;
        }

        // ---- O += P V ----
        #pragma unroll
        for (int kc = 0; kc < 4; kc++) {
            uint32_t pa[4];
            pa[0] = packh2(s[2*kc  ][0], s[2*kc  ][1]);
            pa[1] = packh2(s[2*kc  ][2], s[2*kc  ][3]);
            pa[2] = packh2(s[2*kc+1][0], s[2*kc+1][1]);
            pa[3] = packh2(s[2*kc+1][2], s[2*kc+1][3]);

            uint32_t v4[4][4];
            #pragma unroll
            for (int p = 0; p < 4; p++)
                ldsm_x4_t(v4[p][0], v4[p][1], v4[p][2], v4[p][3],
                          saddr(&Vs[kc*16 + vrow][p*16 + vcol]));
            #pragma unroll
            for (int nt = 0; nt < 8; nt++)
                mma_f16(O[nt], pa, &v4[nt >> 1][(nt & 1) * 2]);
        }
    }

    // ---- epilogue: normalize, write ctx (fp16 single) ----
    const float inv0 = 1.f / l0;
    const float inv1 = 1.f / l1;
    const size_t i0 = ((size_t)bb*SEQ + r0g)*EMBED + hh*HDIM;
    const size_t i1 = ((size_t)bb*SEQ + r1g)*EMBED + hh*HDIM;
    #pragma unroll
    for (int nt = 0; nt < 8; nt++) {
        const int c = nt*8 + (lane & 3)*2;
        *(uint32_t*)&g_C[i0 + c] = packh2(O[nt][0]*inv0, O[nt][1]*inv0);
        *(uint32_t*)&g_C[i1 + c] = packh2(O[nt][2]*inv1, O[nt][3]*inv1);
    }
}

// ---------------------------------------------------------------------------
extern "C" void kernel_launch(void* const* d_in, const int* in_sizes, int n_in,
                              void* d_out, int out_size)
{
    const float* x     = (const float*)d_in[0];   // [B,S,E]
    const float* w_qkv = (const float*)d_in[1];   // [3E,E]
    const float* b_qkv = (const float*)d_in[2];   // [3E]
    const float* w_out = (const float*)d_in[3];   // [E,E]
    const float* b_out = (const float*)d_in[4];   // [E]
    float* out = (float*)d_out;                   // [B,S,E]

    cudaFuncSetAttribute(attn_h, cudaFuncAttributeMaxDynamicSharedMemorySize,
                         ATTN_SMEM_BYTES);
    cudaFuncSetAttribute(gemm_h<0>, cudaFuncAttributeMaxDynamicSharedMemorySize,
                         GEMM_SMEM);
    cudaFuncSetAttribute(gemm_h<1>, cudaFuncAttributeMaxDynamicSharedMemorySize,
                         GEMM_SMEM);

    // 0. convert inputs/weights to fp16
    cvt_inputs<<<8192, 256>>>(x, w_qkv, w_out);

    // 1. QKV projection + head split (fp16 HMMA gemm)
    gemm_h<0><<<dim3((3*EMBED)/128, MROWS/128), 256, GEMM_SMEM>>>(
        b_qkv, nullptr, MROWS, 3*EMBED, EMBED);

    // 2. Causal flash attention (fp16, fp32 accum) -> fp16 ctx
    attn_h<<<dim3(SEQ/128, BATCH*NHEADS), 256, ATTN_SMEM_BYTES>>>();

    // 3. Output projection (fp16 HMMA gemm)
    gemm_h<1><<<dim3(EMBED/128, MROWS/128), 256, GEMM_SMEM>>>(
        b_out, out, MROWS, EMBED, EMBED);
}

// round 13
// speedup vs baseline: 3.4252x; 1.0778x over previous
#include <cuda_runtime.h>
#include <cuda_fp16.h>
#include <cstdint>

#define EMBED   1024
#define NHEADS  16
#define HDIM    64
#define BATCH   2
#define SEQ     2048
#define MROWS   (BATCH*SEQ)   // 4096

#define NEG_INF (-1e30f)

typedef __half fh;

// tcgen05 is NOT usable (harness emits compute_103 PTX; ptxas rejects it).
// All tensor work via mma.sync HMMA, fp16 operands + fp32 accumulators.
// rel_err ~5.2e-4 vs 1e-3 threshold — do not cut precision further.

// ---------------------------------------------------------------------------
// Scratch (device globals). Everything single fp16.
// ---------------------------------------------------------------------------
__device__ fh g_X[(size_t)MROWS*EMBED];
__device__ fh g_Wq[(size_t)3*EMBED*EMBED];
__device__ fh g_Wo[(size_t)EMBED*EMBED];
__device__ fh g_Q[(size_t)MROWS*EMBED];
__device__ fh g_K[(size_t)MROWS*EMBED];
__device__ fh g_V[(size_t)MROWS*EMBED];
__device__ fh g_C[(size_t)MROWS*EMBED];

// ---------------------------------------------------------------------------
// PTX helpers
// ---------------------------------------------------------------------------
__device__ __forceinline__ uint32_t saddr(const void* p) {
    return (uint32_t)__cvta_generic_to_shared(p);
}
__device__ __forceinline__ void cpa16(uint32_t dst, const void* src) {
    asm volatile("cp.async.cg.shared.global [%0], [%1], 16;\n" :: "r"(dst), "l"(src));
}
__device__ __forceinline__ void cpa_commit() {
    asm volatile("cp.async.commit_group;\n");
}
template<int N>
__device__ __forceinline__ void cpa_wait() {
    asm volatile("cp.async.wait_group %0;\n" :: "n"(N));
}
__device__ __forceinline__ void ldsm_x4(uint32_t& r0, uint32_t& r1,
                                        uint32_t& r2, uint32_t& r3, uint32_t a) {
    asm volatile("ldmatrix.sync.aligned.m8n8.x4.shared.b16 {%0,%1,%2,%3}, [%4];"
                 : "=r"(r0), "=r"(r1), "=r"(r2), "=r"(r3) : "r"(a));
}
__device__ __forceinline__ void ldsm_x4_t(uint32_t& r0, uint32_t& r1,
                                          uint32_t& r2, uint32_t& r3, uint32_t a) {
    asm volatile("ldmatrix.sync.aligned.m8n8.x4.trans.shared.b16 {%0,%1,%2,%3}, [%4];"
                 : "=r"(r0), "=r"(r1), "=r"(r2), "=r"(r3) : "r"(a));
}
__device__ __forceinline__ void mma_f16(float* c, const uint32_t* a, const uint32_t* b) {
    asm volatile(
        "mma.sync.aligned.m16n8k16.row.col.f32.f16.f16.f32 "
        "{%0,%1,%2,%3}, {%4,%5,%6,%7}, {%8,%9}, {%0,%1,%2,%3};"
        : "+f"(c[0]), "+f"(c[1]), "+f"(c[2]), "+f"(c[3])
        : "r"(a[0]), "r"(a[1]), "r"(a[2]), "r"(a[3]), "r"(b[0]), "r"(b[1]));
}
__device__ __forceinline__ uint32_t packh2(float a, float b) {
    __half2 h = __floats2half2_rn(a, b);   // a -> low half
    return *(uint32_t*)&h;
}

// ---------------------------------------------------------------------------
// Input conversion pre-pass: x, w_qkv, w_out -> fp16 globals.
// ---------------------------------------------------------------------------
__global__ __launch_bounds__(256)
void cvt_inputs(const float* __restrict__ x, const float* __restrict__ wq,
                const float* __restrict__ wo)
{
    const int i = blockIdx.x * 256 + threadIdx.x;
    const float* src; fh* dst; int off;
    if (i < 1048576)            { src = x;  dst = g_X;  off = i; }
    else if (i < 1048576+786432){ src = wq; dst = g_Wq; off = i - 1048576; }
    else                        { src = wo; dst = g_Wo; off = i - 1835008; }
    float4 f = ((const float4*)src)[off];
    uint2 v; v.x = packh2(f.x, f.y); v.y = packh2(f.z, f.w);
    *(uint2*)(dst + (size_t)off*4) = v;
}

// ---------------------------------------------------------------------------
// Pipelined fp16 HMMA GEMM: out = A @ Bw^T + bias  (unchanged from R11)
// 256 threads, CTA tile 128x128, 8 warps (2m x 4n), warp tile 64x32.
// K-step 32, 2-stage cp.async, 2 CTAs/SM.
// ---------------------------------------------------------------------------
#define GSTAGE_B  20480
#define GEMM_SMEM (2*GSTAGE_B)   // 40960

template<int MODE>
__global__ __launch_bounds__(256, 2)
void gemm_h(const float* __restrict__ bias, float* __restrict__ C,
            int M, int N, int K)
{
    extern __shared__ fh sm[];
    const uint32_t smem0 = saddr(sm);

    const fh* Ap = (MODE == 0) ? g_X : g_C;
    const fh* Bp = (MODE == 0) ? g_Wq : g_Wo;

    const int tid  = threadIdx.x;
    const int lane = tid & 31;
    const int warp = tid >> 5;
    const int wm   = warp >> 2;
    const int wn   = warp & 3;
    const int bm   = blockIdx.y * 128;
    const int bn   = blockIdx.x * 128;

    const int lr    = tid >> 1;
    const int half_ = tid & 1;

    const fh* aP = Ap + (size_t)(bm + lr) * K + half_*16;
    const fh* bP = Bp + (size_t)(bn + lr) * K + half_*16;
    const uint32_t adst = smem0 + lr*80 + half_*32;
    const uint32_t bdst = adst + 10240;

    const int nsteps = K >> 5;

    auto copy_stage = [&](int k0, int stg) {
        const uint32_t d = stg * GSTAGE_B;
        cpa16(adst + d,      aP + k0);  cpa16(adst + d + 16, aP + k0 + 8);
        cpa16(bdst + d,      bP + k0);  cpa16(bdst + d + 16, bP + k0 + 8);
    };

    float acc[16][4];
    #pragma unroll
    for (int i = 0; i < 16; i++)
        #pragma unroll
        for (int j = 0; j < 4; j++) acc[i][j] = 0.f;

    const int arow = wm*64 + (lane & 15);
    const int acol = ((lane >> 4) & 1) * 8;
    const int brow = wn*32 + (lane & 7) + ((lane >> 4) & 1) * 8;
    const int bcol = ((lane >> 3) & 1) * 8;
    const uint32_t aoff = (uint32_t)(arow*80 + acol*2);
    const uint32_t boff = (uint32_t)(10240 + brow*80 + bcol*2);

    copy_stage(0, 0);  cpa_commit();

    for (int ks = 0; ks < nsteps; ks++) {
        const int nk = ks + 1;
        if (nk < nsteps) copy_stage(nk*32, nk & 1);
        cpa_commit();
        cpa_wait<1>();
        __syncthreads();

        const uint32_t base = smem0 + (ks & 1) * GSTAGE_B;

        #pragma unroll
        for (int kk = 0; kk < 2; kk++) {
            const uint32_t ab  = base + aoff + kk*32;
            const uint32_t bbx = base + boff + kk*32;
            uint32_t bh[2][4];
            #pragma unroll
            for (int p = 0; p < 2; p++)
                ldsm_x4(bh[p][0], bh[p][1], bh[p][2], bh[p][3], bbx + p*1280);
            #pragma unroll
            for (int t = 0; t < 4; t++) {
                uint32_t ah[4];
                ldsm_x4(ah[0], ah[1], ah[2], ah[3], ab + t*1280);
                #pragma unroll
                for (int n = 0; n < 4; n++)
                    mma_f16(acc[t*4 + n], ah, &bh[n >> 1][(n & 1) * 2]);
            }
        }
        __syncthreads();
    }

    // epilogue
    #pragma unroll
    for (int t = 0; t < 4; t++) {
        const int r0 = bm + wm*64 + t*16 + (lane >> 2);
        #pragma unroll
        for (int n = 0; n < 4; n++) {
            const int col = bn + wn*32 + n*8 + (lane & 3)*2;
            const float b0v = bias[col], b1v = bias[col + 1];
            const float* c = acc[t*4 + n];
            if (MODE == 0) {
                const int sel = col >> 10;      // 0=Q 1=K 2=V
                const int e   = col & 1023;
                fh* pq = (sel == 0) ? g_Q : (sel == 1) ? g_K : g_V;
                const int hh = e >> 6, dd = e & 63;
                #pragma unroll
                for (int rr = 0; rr < 2; rr++) {
                    const int row = r0 + rr*8;
                    const int bbv = row >> 11, ss = row & 2047;
                    const size_t idx = (((size_t)(bbv*NHEADS + hh))*SEQ + ss)*HDIM + dd;
                    *(uint32_t*)&pq[idx] = packh2(c[rr*2] + b0v, c[rr*2+1] + b1v);
                }
            } else {
                float2 v0; v0.x = c[0] + b0v; v0.y = c[1] + b1v;
                float2 v1; v1.x = c[2] + b0v; v1.y = c[3] + b1v;
                *(float2*)&C[(size_t)r0       * N + col] = v0;
                *(float2*)&C[(size_t)(r0 + 8) * N + col] = v1;
            }
        }
    }
}

// ---------------------------------------------------------------------------
// fp16 flash attention (causal), fp32 accumulators.
// NEW: 2-stage double-buffered K/V cp.async pipeline — prefetch tile kt+1
// while computing tile kt (loads were fully latency-exposed before).
// smem (halves): Q[128][72] @0, K stages @9216+stg*4608, V @18432+stg*4608.
// Total 27648 halves = 55296 B.
// ---------------------------------------------------------------------------
#define ATTN_SMEM_BYTES 55296

__global__ __launch_bounds__(256, 1)
void attn_h()
{
    extern __shared__ fh sb[];
    fh (*Qs)[72] = (fh(*)[72])(sb);

    const int qt   = (int)(gridDim.x - 1) - (int)blockIdx.x;   // big tiles first
    const int bhid = blockIdx.y;
    const int bb   = bhid / NHEADS;
    const int hh   = bhid % NHEADS;

    const size_t hb = (size_t)bhid * SEQ * HDIM;

    const int tid  = threadIdx.x;
    const int lane = tid & 31;
    const int w    = tid >> 5;
    const int qbase = qt * 128;

    const int kr = tid >> 2, q4 = tid & 3;

    // K/V tile loader into a given stage
    auto load_kv = [&](int kt, int stg) {
        const size_t srcoff = hb + (size_t)(kt*64 + kr)*HDIM + q4*16;
        const uint32_t doff = (uint32_t)(stg*9216 + kr*144 + q4*32);
        const uint32_t dk = saddr(sb + 9216)  + doff;
        const uint32_t dv = saddr(sb + 18432) + doff;
        cpa16(dk, g_K + srcoff);  cpa16(dk + 16, g_K + srcoff + 8);
        cpa16(dv, g_V + srcoff);  cpa16(dv + 16, g_V + srcoff + 8);
    };

    const int nktiles = 2*qt + 2;

    // ---- prologue: load Q (group A), prefetch K/V tile 0 (group B) ----
    {
        const int lr = tid >> 1, hx = tid & 1;
        const fh* qsrc = g_Q + hb + (size_t)(qbase + lr)*HDIM + hx*32;
        const uint32_t dq = saddr(&Qs[lr][hx*32]);
        #pragma unroll
        for (int u = 0; u < 4; u++)
            cpa16(dq + u*16, qsrc + u*8);
        cpa_commit();                 // group A (Q)
    }
    load_kv(0, 0);
    cpa_commit();                     // group B (KV tile 0)
    cpa_wait<1>();                    // Q complete (B may be in flight)
    __syncthreads();

    // ---- Q fragments (registers for the whole kernel) ----
    uint32_t qf[4][4];
    {
        const int arow = w*16 + (lane & 15);
        const int acol = ((lane >> 4) & 1) * 8;
        #pragma unroll
        for (int kc = 0; kc < 4; kc++)
            ldsm_x4(qf[kc][0], qf[kc][1], qf[kc][2], qf[kc][3],
                    saddr(&Qs[arow][kc*16 + acol]));
    }

    float O[8][4];
    #pragma unroll
    for (int nt = 0; nt < 8; nt++)
        #pragma unroll
        for (int e = 0; e < 4; e++) O[nt][e] = 0.f;

    float m0 = NEG_INF, m1 = NEG_INF, l0 = 0.f, l1 = 0.f;
    const int r0g = qbase + w*16 + (lane >> 2);
    const int r1g = r0g + 8;
    const int wr  = qbase + w*16;

    const int krow = (lane & 7) + ((lane >> 4) & 1) * 8;
    const int kcol = ((lane >> 3) & 1) * 8;
    const int vrow = (lane & 7) + ((lane >> 3) & 1) * 8;
    const int vcol = ((lane >> 4) & 1) * 8;

    for (int kt = 0; kt < nktiles; kt++) {
        const int kbase = kt * 64;
        __syncthreads();   // all warps done reading the stage we're about to refill

        // prefetch next tile into the alternate stage, then wait for current
        const int nk = kt + 1;
        if (nk < nktiles) load_kv(nk, nk & 1);
        cpa_commit();
        cpa_wait<1>();     // current tile's group complete; next may be in flight
        __syncthreads();

        if (wr + 15 < kbase) continue;   // warp fully masked for this tile

        const uint32_t kbs = saddr(sb + 9216)  + (kt & 1)*9216;
        const uint32_t vbs = saddr(sb + 18432) + (kt & 1)*9216;

        // ---- S = Q K^T ----
        float s[8][4];
        #pragma unroll
        for (int nt = 0; nt < 8; nt++)
            #pragma unroll
            for (int e = 0; e < 4; e++) s[nt][e] = 0.f;

        #pragma unroll
        for (int kc = 0; kc < 4; kc++) {
            uint32_t k4[4][4];
            #pragma unroll
            for (int p = 0; p < 4; p++)
                ldsm_x4(k4[p][0], k4[p][1], k4[p][2], k4[p][3],
                        kbs + (uint32_t)((p*16 + krow)*144 + (kc*16 + kcol)*2));
            #pragma unroll
            for (int nt = 0; nt < 8; nt++)
                mma_f16(s[nt], qf[kc], &k4[nt >> 1][(nt & 1) * 2]);
        }

        // scale + causal mask
        #pragma unroll
        for (int nt = 0; nt < 8; nt++)
            #pragma unroll
            for (int e = 0; e < 4; e++) s[nt][e] *= 0.125f;

        if (kbase + 63 > wr) {
            #pragma unroll
            for (int nt = 0; nt < 8; nt++) {
                const int c0 = kbase + nt*8 + ((lane & 3) << 1);
                if (c0     > r0g) s[nt][0] = NEG_INF;
                if (c0 + 1 > r0g) s[nt][1] = NEG_INF;
                if (c0     > r1g) s[nt][2] = NEG_INF;
                if (c0 + 1 > r1g) s[nt][3] = NEG_INF;
            }
        }

        // ---- online softmax ----
        float mx0 = NEG_INF, mx1 = NEG_INF;
        #pragma unroll
        for (int nt = 0; nt < 8; nt++) {
            mx0 = fmaxf(mx0, fmaxf(s[nt][0], s[nt][1]));
            mx1 = fmaxf(mx1, fmaxf(s[nt][2], s[nt][3]));
        }
        mx0 = fmaxf(mx0, __shfl_xor_sync(0xffffffffu, mx0, 1));
        mx0 = fmaxf(mx0, __shfl_xor_sync(0xffffffffu, mx0, 2));
        mx1 = fmaxf(mx1, __shfl_xor_sync(0xffffffffu, mx1, 1));
        mx1 = fmaxf(mx1, __shfl_xor_sync(0xffffffffu, mx1, 2));

        const float nm0 = fmaxf(m0, mx0);
        const float nm1 = fmaxf(m1, mx1);
        const float f0 = __expf(m0 - nm0);
        const float f1 = __expf(m1 - nm1);

        float ps0 = 0.f, ps1 = 0.f;
        #pragma unroll
        for (int nt = 0; nt < 8; nt++) {
            s[nt][0] = __expf(s[nt][0] - nm0);
            s[nt][1] = __expf(s[nt][1] - nm0);
            s[nt][2] = __expf(s[nt][2] - nm1);
            s[nt][3] = __expf(s[nt][3] - nm1);
            ps0 += s[nt][0] + s[nt][1];
            ps1 += s[nt][2] + s[nt][3];
        }
        ps0 += __shfl_xor_sync(0xffffffffu, ps0, 1);
        ps0 += __shfl_xor_sync(0xffffffffu, ps0, 2);
        ps1 += __shfl_xor_sync(0xffffffffu, ps1, 1);
        ps1 += __shfl_xor_sync(0xffffffffu, ps1, 2);

        l0 = l0 * f0 + ps0;  m0 = nm0;
        l1 = l1 * f1 + ps1;  m1 = nm1;

        #pragma unroll
        for (int nt = 0; nt < 8; nt++) {
            O[nt][0] *= f0; O[nt][1] *= f0;
            O[nt][2] *= f1; O[nt][3] *= f1;
        }

        // ---- O += P V ----
        #pragma unroll
        for (int kc = 0; kc < 4; kc++) {
            uint32_t pa[4];
            pa[0] = packh2(s[2*kc  ][0], s[2*kc  ][1]);
            pa[1] = packh2(s[2*kc  ][2], s[2*kc  ][3]);
            pa[2] = packh2(s[2*kc+1][0], s[2*kc+1][1]);
            pa[3] = packh2(s[2*kc+1][2], s[2*kc+1][3]);

            uint32_t v4[4][4];
            #pragma unroll
            for (int p = 0; p < 4; p++)
                ldsm_x4_t(v4[p][0], v4[p][1], v4[p][2], v4[p][3],
                          vbs + (uint32_t)((kc*16 + vrow)*144 + (p*16 + vcol)*2));
            #pragma unroll
            for (int nt = 0; nt < 8; nt++)
                mma_f16(O[nt], pa, &v4[nt >> 1][(nt & 1) * 2]);
        }
    }

    // ---- epilogue: normalize, write ctx (fp16) ----
    const float inv0 = 1.f / l0;
    const float inv1 = 1.f / l1;
    const size_t i0 = ((size_t)bb*SEQ + r0g)*EMBED + hh*HDIM;
    const size_t i1 = ((size_t)bb*SEQ + r1g)*EMBED + hh*HDIM;
    #pragma unroll
    for (int nt = 0; nt < 8; nt++) {
        const int c = nt*8 + (lane & 3)*2;
        *(uint32_t*)&g_C[i0 + c] = packh2(O[nt][0]*inv0, O[nt][1]*inv0);
        *(uint32_t*)&g_C[i1 + c] = packh2(O[nt][2]*inv1, O[nt][3]*inv1);
    }
}

// ---------------------------------------------------------------------------
extern "C" void kernel_launch(void* const* d_in, const int* in_sizes, int n_in,
                              void* d_out, int out_size)
{
    const float* x     = (const float*)d_in[0];   // [B,S,E]
    const float* w_qkv = (const float*)d_in[1];   // [3E,E]
    const float* b_qkv = (const float*)d_in[2];   // [3E]
    const float* w_out = (const float*)d_in[3];   // [E,E]
    const float* b_out = (const float*)d_in[4];   // [E]
    float* out = (float*)d_out;                   // [B,S,E]

    cudaFuncSetAttribute(attn_h, cudaFuncAttributeMaxDynamicSharedMemorySize,
                         ATTN_SMEM_BYTES);
    cudaFuncSetAttribute(gemm_h<0>, cudaFuncAttributeMaxDynamicSharedMemorySize,
                         GEMM_SMEM);
    cudaFuncSetAttribute(gemm_h<1>, cudaFuncAttributeMaxDynamicSharedMemorySize,
                         GEMM_SMEM);

    // 0. convert inputs/weights to fp16
    cvt_inputs<<<8192, 256>>>(x, w_qkv, w_out);

    // 1. QKV projection + head split (fp16 HMMA gemm)
    gemm_h<0><<<dim3((3*EMBED)/128, MROWS/128), 256, GEMM_SMEM>>>(
        b_qkv, nullptr, MROWS, 3*EMBED, EMBED);

    // 2. Causal flash attention (fp16, fp32 accum, pipelined K/V) -> fp16 ctx
    attn_h<<<dim3(SEQ/128, BATCH*NHEADS), 256, ATTN_SMEM_BYTES>>>();

    // 3. Output projection (fp16 HMMA gemm)
    gemm_h<1><<<dim3(EMBED/128, MROWS/128), 256, GEMM_SMEM>>>(
        b_out, out, MROWS, EMBED, EMBED);
}